// round 7
// baseline (speedup 1.0000x reference)
#include <cuda_runtime.h>

#define BATCH 64
#define CIN   96
#define CHID  256
#define COUT  80
#define TLEN  2048
#define BCH   16          // batch chunk size
#define NCH   (BATCH/BCH) // 4 chunks

// ---- scratch (allocation-free rule: __device__ globals) ----
static __device__ float    g_z1[(size_t)BATCH * TLEN * CHID];          // 128 MiB
static __device__ float    g_z2[(size_t)BATCH * TLEN * COUT];          // 40 MiB (layout [b][j][t])
static __device__ unsigned g_xbits[(size_t)BATCH * TLEN * 4];          // 2 MiB
static __device__ unsigned g_s1bits[(size_t)BATCH * TLEN * (CHID/32)]; // 4 MiB

// =====================================================================
// K0: build 96-bit input-activity masks per (b,t). Coalesced LDGs.
// =====================================================================
__global__ __launch_bounds__(256) void k0_xbits(const float* __restrict__ x, int b0) {
    const int gid = blockIdx.x * 256 + threadIdx.x;   // 0 .. BCH*2048-1
    const int b = b0 + (gid >> 11);
    const int t = gid & 2047;
    const float* xp = x + (size_t)b * CIN * TLEN + t;
    unsigned m0 = 0, m1 = 0, m2 = 0;
    #pragma unroll
    for (int i = 0; i < 32; i++) if (__ldg(xp + (size_t)i * TLEN) != 0.0f)        m0 |= 1u << i;
    #pragma unroll
    for (int i = 0; i < 32; i++) if (__ldg(xp + (size_t)(i + 32) * TLEN) != 0.0f) m1 |= 1u << i;
    #pragma unroll
    for (int i = 0; i < 32; i++) if (__ldg(xp + (size_t)(i + 64) * TLEN) != 0.0f) m2 |= 1u << i;
    *(uint4*)&g_xbits[((size_t)b * TLEN + t) * 4] = make_uint4(m0, m1, m2, 0u);
}

// =====================================================================
// K1: layer-1 sparse GEMM. z1[b][t][o] = sum_{i active, ascending} W1[o][i]
// CTA = (t-chunk 128, b); 1024 threads. Thread owns 4 adjacent o
// (LDS.128). Lists = uint32 byte offsets i*1024, zero-padded to x4
// (dummy row 96 = 0). Bit-exact ascending-i order per o.
// =====================================================================
#define K1_T 128
__global__ __launch_bounds__(1024) void k1_gemm1(const float* __restrict__ W1, int b0) {
    extern __shared__ char sm[];
    float*    w1t    = (float*)sm;                   // [97][256] = 99328 B
    unsigned* lists  = (unsigned*)(sm + 99328);      // [128][104] u32 = 53248 B
    int*      counts = (int*)(sm + 152576);          // [128]

    const int tid = threadIdx.x;
    const int t0  = blockIdx.x * K1_T;
    const int b   = b0 + blockIdx.y;

    for (int idx = tid; idx < CHID * CIN; idx += 1024) {
        int o = idx / CIN, i = idx % CIN;
        w1t[i * 256 + o] = W1[idx];
    }
    if (tid < 256) w1t[96 * 256 + tid] = 0.0f;

    if (tid < K1_T) {
        uint4 mw = *(const uint4*)&g_xbits[((size_t)b * TLEN + t0 + tid) * 4];
        unsigned* L = lists + tid * 104;
        int c = 0;
        unsigned m = mw.x;
        while (m) { int k = __ffs(m) - 1; m &= m - 1; L[c++] = (unsigned)(k << 10); }
        m = mw.y;
        while (m) { int k = __ffs(m) - 1; m &= m - 1; L[c++] = (unsigned)((k + 32) << 10); }
        m = mw.z;
        while (m) { int k = __ffs(m) - 1; m &= m - 1; L[c++] = (unsigned)((k + 64) << 10); }
        while (c & 3) L[c++] = (unsigned)(96 << 10);
        counts[tid] = c;
    }
    __syncthreads();

    const int grp = tid >> 6;          // 0..15
    const int o   = (tid & 63) * 4;
    const char* wb = (const char*)w1t + o * 4;
    float* zp = g_z1 + ((size_t)b * TLEN + t0) * CHID + o;

    for (int tt = grp; tt < K1_T; tt += 16) {
        const unsigned* L = lists + tt * 104;
        const int cnt = counts[tt];
        float a0 = 0.0f, a1 = 0.0f, a2 = 0.0f, a3 = 0.0f;
        for (int p = 0; p < cnt; p += 4) {
            uint4 e = *(const uint4*)(L + p);
            float4 w0 = *(const float4*)(wb + e.x);
            float4 w1 = *(const float4*)(wb + e.y);
            float4 w2 = *(const float4*)(wb + e.z);
            float4 w3 = *(const float4*)(wb + e.w);
            a0 += w0.x; a1 += w0.y; a2 += w0.z; a3 += w0.w;
            a0 += w1.x; a1 += w1.y; a2 += w1.z; a3 += w1.w;
            a0 += w2.x; a1 += w2.y; a2 += w2.z; a3 += w2.w;
            a0 += w3.x; a1 += w3.y; a2 += w3.z; a3 += w3.w;
        }
        *(float4*)(zp + (size_t)tt * CHID) = make_float4(a0, a1, a2, a3);
    }
}

// =====================================================================
// LIF batch processors.  v = fma(v, 0.95f, z) — matches XLA contraction.
// =====================================================================
__device__ __forceinline__ void proc32_bits(float& v, const float (&z)[32],
                                            int tbase, float* __restrict__ so,
                                            unsigned* __restrict__ bw, int lane) {
    unsigned keep = 0;
    #pragma unroll
    for (int u8 = 0; u8 < 32; u8 += 8) {
        float sv[8];
        #pragma unroll
        for (int u = 0; u < 8; u++) {
            const int st = u8 + u;
            v = __fmaf_rn(v, 0.95f, z[st]);
            bool sp = (v >= 1.0f);
            sv[u] = sp ? 1.0f : 0.0f;
            unsigned bal = __ballot_sync(0xffffffffu, sp);
            keep = (lane == st) ? bal : keep;
            v = sp ? 0.0f : v;
        }
        *(float4*)(so + tbase + u8)     = make_float4(sv[0], sv[1], sv[2], sv[3]);
        *(float4*)(so + tbase + u8 + 4) = make_float4(sv[4], sv[5], sv[6], sv[7]);
    }
    bw[(size_t)(tbase + lane) * (CHID/32)] = keep;
}

__device__ __forceinline__ void proc32(float& v, const float (&z)[32],
                                       int tbase, float* __restrict__ so) {
    #pragma unroll
    for (int u8 = 0; u8 < 32; u8 += 8) {
        float sv[8];
        #pragma unroll
        for (int u = 0; u < 8; u++) {
            v = __fmaf_rn(v, 0.95f, z[u8 + u]);
            bool sp = (v >= 1.0f);
            sv[u] = sp ? 1.0f : 0.0f;
            v = sp ? 0.0f : v;
        }
        *(float4*)(so + tbase + u8)     = make_float4(sv[0], sv[1], sv[2], sv[3]);
        *(float4*)(so + tbase + u8 + 4) = make_float4(sv[4], sv[5], sv[6], sv[7]);
    }
}

// =====================================================================
// K2: layer-1 LIF scan. (BCH*256)/64 CTAs of 64 thr.
// 4 rotating 32-step register buffers (prefetch distance 3).
// =====================================================================
#define LD32(dst, zp, t) { _Pragma("unroll") \
    for (int u = 0; u < 32; u++) dst[u] = __ldg(zp + (size_t)((t) + u) * CHID); }

__global__ __launch_bounds__(64) void k2_scan1(float* __restrict__ out, int b0) {
    const int gid  = blockIdx.x * 64 + threadIdx.x;
    const int b    = b0 + (gid >> 8);
    const int o    = gid & 255;
    const int lane = o & 31;
    const float* z  = g_z1 + (size_t)b * TLEN * CHID + o;
    float*       so = out + ((size_t)b * CHID + o) * TLEN;
    unsigned*    bw = g_s1bits + (size_t)b * TLEN * (CHID/32) + (o >> 5);

    float A[32], B[32], C[32], D[32];
    float v = 0.0f;
    LD32(A, z, 0); LD32(B, z, 32); LD32(C, z, 64);

    for (int bi = 0; bi < 64; bi += 4) {
        const int t = bi * 32;
        if (bi + 3 < 64) LD32(D, z, t + 96);
        proc32_bits(v, A, t, so, bw, lane);
        if (bi + 4 < 64) LD32(A, z, t + 128);
        proc32_bits(v, B, t + 32, so, bw, lane);
        if (bi + 5 < 64) LD32(B, z, t + 160);
        proc32_bits(v, C, t + 64, so, bw, lane);
        if (bi + 6 < 64) LD32(C, z, t + 192);
        proc32_bits(v, D, t + 96, so, bw, lane);
    }
}

// =====================================================================
// K3: layer-2 sparse GEMM from spike bits. CTA = (t-chunk 64, b);
// 768 threads = 8 groups x 96 lanes (3 full warps -> warp-uniform masks),
// lanes r>=80 fully gated off (no wasted LDS). Results staged in an smem
// tile (stride 81: conflict-free writes AND transpose reads), then stored
// TRANSPOSED to g_z2[b][j][t] as float4 so K4 reads contiguously.
// =====================================================================
#define K3_T 64
__global__ __launch_bounds__(768) void k3_gemm2(const float* __restrict__ W2, int b0) {
    extern __shared__ char sm[];
    float*    w2t    = (float*)sm;                   // [257][81]+pad = 83344 B
    unsigned* lists  = (unsigned*)(sm + 83344);      // [64][264] u32 = 67584 B
    int*      counts = (int*)(sm + 150928);          // [64] = 256 B
    float*    ztile  = (float*)(sm + 151184);        // [64][81] = 20736 B

    const int tid = threadIdx.x;
    const int t0  = blockIdx.x * K3_T;
    const int b   = b0 + blockIdx.y;

    for (int idx = tid; idx < COUT * CHID; idx += 768) {
        int j = idx / CHID, o = idx % CHID;
        w2t[o * 81 + j] = W2[idx];
    }
    if (tid < 100) w2t[256 * 81 + tid] = 0.0f;

    if (tid < K3_T) {
        const unsigned* sb = g_s1bits + ((size_t)b * TLEN + t0 + tid) * 8;
        unsigned* L = lists + tid * 264;
        int c = 0;
        #pragma unroll
        for (int w = 0; w < 8; w++) {
            unsigned m = sb[w];
            while (m) {
                int k = __ffs(m) - 1;
                m &= m - 1;
                L[c++] = (unsigned)(((w << 5) + k) * 324);
            }
        }
        while (c & 3) L[c++] = (unsigned)(256 * 324);
        counts[tid] = c;
    }
    __syncthreads();

    const int grp = tid / 96;            // 0..7 (3 full warps each)
    const int r   = tid % 96;

    if (r < COUT) {                      // lanes 80..95 issue nothing
        const char* wb = (const char*)w2t + r * 4;
        for (int q = grp; q < K3_T / 2; q += 8) {
            const int tt = 2 * q;
            const unsigned* L0 = lists + tt * 264;
            const unsigned* L1 = L0 + 264;
            const int c0 = counts[tt], c1 = counts[tt + 1];
            const int cmin = c0 < c1 ? c0 : c1;
            float a0 = 0.0f, a1 = 0.0f;
            int p = 0;
            for (; p < cmin; p += 4) {
                uint4 e0 = *(const uint4*)(L0 + p);
                uint4 e1 = *(const uint4*)(L1 + p);
                a0 += *(const float*)(wb + e0.x);  a1 += *(const float*)(wb + e1.x);
                a0 += *(const float*)(wb + e0.y);  a1 += *(const float*)(wb + e1.y);
                a0 += *(const float*)(wb + e0.z);  a1 += *(const float*)(wb + e1.z);
                a0 += *(const float*)(wb + e0.w);  a1 += *(const float*)(wb + e1.w);
            }
            for (; p < c0; p += 4) {
                uint4 e0 = *(const uint4*)(L0 + p);
                a0 += *(const float*)(wb + e0.x);  a0 += *(const float*)(wb + e0.y);
                a0 += *(const float*)(wb + e0.z);  a0 += *(const float*)(wb + e0.w);
            }
            for (; p < c1; p += 4) {
                uint4 e1 = *(const uint4*)(L1 + p);
                a1 += *(const float*)(wb + e1.x);  a1 += *(const float*)(wb + e1.y);
                a1 += *(const float*)(wb + e1.z);  a1 += *(const float*)(wb + e1.w);
            }
            ztile[tt * 81 + r]       = a0;
            ztile[(tt + 1) * 81 + r] = a1;
        }
    }
    __syncthreads();

    // transposed store-out: g_z2[b][j][t0+4q..+3], float4, coalesced
    float* zo = g_z2 + (size_t)b * COUT * TLEN + t0;
    for (int idx = tid; idx < COUT * (K3_T / 4); idx += 768) {
        int j = idx >> 4, q = idx & 15;
        float4 vv = make_float4(ztile[(4 * q + 0) * 81 + j],
                                ztile[(4 * q + 1) * 81 + j],
                                ztile[(4 * q + 2) * 81 + j],
                                ztile[(4 * q + 3) * 81 + j]);
        *(float4*)(zo + (size_t)j * TLEN + 4 * q) = vv;
    }
}

// =====================================================================
// K4: layer-2 LIF scan. g_z2 is [b][j][t] -> contiguous float4 loads.
// =====================================================================
#define LD32C(dst, zp, t) { _Pragma("unroll") \
    for (int u = 0; u < 8; u++) *(float4*)((dst) + 4 * u) = \
        __ldg((const float4*)((zp) + (t)) + u); }

__global__ __launch_bounds__(32) void k4_scan2(float* __restrict__ out, int b0) {
    const int gid = blockIdx.x * 32 + threadIdx.x;   // 0..BCH*80-1
    const int b = b0 + gid / COUT;
    const int j = gid % COUT;
    const float* z  = g_z2 + ((size_t)b * COUT + j) * TLEN;
    float*       so = out + (size_t)BATCH * CHID * TLEN
                          + ((size_t)b * COUT + j) * TLEN;

    float A[32], B[32], C[32], D[32];
    float v = 0.0f;
    LD32C(A, z, 0); LD32C(B, z, 32); LD32C(C, z, 64);

    for (int bi = 0; bi < 64; bi += 4) {
        const int t = bi * 32;
        if (bi + 3 < 64) LD32C(D, z, t + 96);
        proc32(v, A, t, so);
        if (bi + 4 < 64) LD32C(A, z, t + 128);
        proc32(v, B, t + 32, so);
        if (bi + 5 < 64) LD32C(B, z, t + 160);
        proc32(v, C, t + 64, so);
        if (bi + 6 < 64) LD32C(C, z, t + 192);
        proc32(v, D, t + 96, so);
    }
}

// =====================================================================
// Stream/event pool: built ONCE on the (uncaptured) correctness call,
// reused by the capture call. Host-side resources only — no device mem.
// =====================================================================
struct HxStreams {
    cudaStream_t s[2];
    cudaEvent_t  root, fin[2];
    HxStreams() {
        for (int i = 0; i < 2; i++)
            cudaStreamCreateWithFlags(&s[i], cudaStreamNonBlocking);
        cudaEventCreateWithFlags(&root, cudaEventDisableTiming);
        for (int i = 0; i < 2; i++)
            cudaEventCreateWithFlags(&fin[i], cudaEventDisableTiming);
    }
};
static HxStreams& hx() { static HxStreams S; return S; }

extern "C" void kernel_launch(void* const* d_in, const int* in_sizes, int n_in,
                              void* d_out, int out_size) {
    const float* x  = (const float*)d_in[0];   // [64, 96, 2048]
    const float* W1 = (const float*)d_in[1];   // [256, 96]
    const float* W2 = (const float*)d_in[2];   // [80, 256]
    float* out = (float*)d_out;                // spk1 ++ spk2

    const int smem1 = 99328 + 53248 + 512;             // 153088
    const int smem3 = 151184 + 20736;                  // 171920
    cudaFuncSetAttribute(k1_gemm1, cudaFuncAttributeMaxDynamicSharedMemorySize, smem1);
    cudaFuncSetAttribute(k3_gemm2, cudaFuncAttributeMaxDynamicSharedMemorySize, smem3);

    HxStreams& S = hx();

    // fork both worker streams off the captured origin stream
    cudaEventRecord(S.root, 0);
    cudaStreamWaitEvent(S.s[0], S.root, 0);
    cudaStreamWaitEvent(S.s[1], S.root, 0);

    for (int c = 0; c < NCH; c++) {
        cudaStream_t st = S.s[c & 1];
        const int b0 = c * BCH;
        k0_xbits<<<(BCH * TLEN) / 256, 256, 0, st>>>(x, b0);
        k1_gemm1<<<dim3(TLEN / K1_T, BCH), 1024, smem1, st>>>(W1, b0);
        k2_scan1<<<(BCH * CHID) / 64, 64, 0, st>>>(out, b0);
        k3_gemm2<<<dim3(TLEN / K3_T, BCH), 768, smem3, st>>>(W2, b0);
        k4_scan2<<<(BCH * COUT) / 32, 32, 0, st>>>(out, b0);
    }

    // join back to the origin stream
    cudaEventRecord(S.fin[0], S.s[0]);
    cudaEventRecord(S.fin[1], S.s[1]);
    cudaStreamWaitEvent(0, S.fin[0], 0);
    cudaStreamWaitEvent(0, S.fin[1], 0);
}

// round 8
// speedup vs baseline: 1.5127x; 1.5127x over previous
#include <cuda_runtime.h>

#define BATCH 64
#define CIN   96
#define CHID  256
#define COUT  80
#define TLEN  2048

// ---- scratch (allocation-free rule: __device__ globals) ----
static __device__ float    g_z1[(size_t)BATCH * TLEN * CHID];          // 128 MiB  [b][t][o]
static __device__ float    g_z2[(size_t)BATCH * TLEN * COUT];          // 40 MiB   [b][j][t]
static __device__ unsigned g_xbits[(size_t)BATCH * TLEN * 4];          // 2 MiB
static __device__ unsigned g_s1bits[(size_t)BATCH * TLEN * (CHID/32)]; // 4 MiB

// =====================================================================
// K0: build 96-bit input-activity masks per (b,t). Coalesced LDGs.
// =====================================================================
__global__ __launch_bounds__(256) void k0_xbits(const float* __restrict__ x) {
    const int gid = blockIdx.x * 256 + threadIdx.x;   // 0 .. 64*2048-1
    const int b = gid >> 11;
    const int t = gid & 2047;
    const float* xp = x + (size_t)b * CIN * TLEN + t;
    unsigned m0 = 0, m1 = 0, m2 = 0;
    #pragma unroll
    for (int i = 0; i < 32; i++) if (__ldg(xp + (size_t)i * TLEN) != 0.0f)        m0 |= 1u << i;
    #pragma unroll
    for (int i = 0; i < 32; i++) if (__ldg(xp + (size_t)(i + 32) * TLEN) != 0.0f) m1 |= 1u << i;
    #pragma unroll
    for (int i = 0; i < 32; i++) if (__ldg(xp + (size_t)(i + 64) * TLEN) != 0.0f) m2 |= 1u << i;
    *(uint4*)&g_xbits[(size_t)gid * 4] = make_uint4(m0, m1, m2, 0u);
}

// =====================================================================
// K1: layer-1 sparse GEMM. z1[b][t][o] = sum_{i active, ascending} W1[o][i]
// CTA = (t-chunk 128, b); 1024 threads. Thread owns 4 adjacent o
// (LDS.128, 512B contiguous per warp -> conflict-free).
// w1t row stride = 260 floats (1040 B): 16B-aligned for LDS.128 and the
// weight-load STS drops from 32-way to 4-way bank conflicts (stride 1024B
// was a full 32-way collision -> ~24k wasted crossbar cyc/CTA).
// Lists = uint32 BYTE offsets i*1040, zero-padded x4 (dummy row 96 = 0).
// Bit-exact ascending-i order per o.
// =====================================================================
#define K1_T 128
#define W1STR 1040                     // bytes per w1t row (260 floats)
__global__ __launch_bounds__(1024) void k1_gemm1(const float* __restrict__ W1) {
    extern __shared__ char sm[];
    float*    w1t    = (float*)sm;                   // [97][260] = 100880 B
    unsigned* lists  = (unsigned*)(sm + 100896);     // [128][104] u32 = 53248 B
    int*      counts = (int*)(sm + 154144);          // [128]

    const int tid = threadIdx.x;
    const int t0  = blockIdx.x * K1_T;
    const int b   = blockIdx.y;

    // W1 [256][96] row-major, coalesced LDG; STS stride 260 (4-way max)
    for (int idx = tid; idx < CHID * CIN; idx += 1024) {
        int o = idx / CIN, i = idx % CIN;
        w1t[i * 260 + o] = W1[idx];
    }
    if (tid < 256) w1t[96 * 260 + tid] = 0.0f;   // dummy row covers bytes 0..1023

    if (tid < K1_T) {  // build ascending byte-offset list for step t0+tid
        uint4 mw = *(const uint4*)&g_xbits[((size_t)b * TLEN + t0 + tid) * 4];
        unsigned* L = lists + tid * 104;
        int c = 0;
        unsigned m = mw.x;
        while (m) { int k = __ffs(m) - 1; m &= m - 1; L[c++] = (unsigned)(k * W1STR); }
        m = mw.y;
        while (m) { int k = __ffs(m) - 1; m &= m - 1; L[c++] = (unsigned)((k + 32) * W1STR); }
        m = mw.z;
        while (m) { int k = __ffs(m) - 1; m &= m - 1; L[c++] = (unsigned)((k + 64) * W1STR); }
        while (c & 3) L[c++] = (unsigned)(96 * W1STR);
        counts[tid] = c;
    }
    __syncthreads();

    const int grp = tid >> 6;          // 0..15: step interleave (2 warps each)
    const int o   = (tid & 63) * 4;    // 4 adjacent outputs
    const char* wb = (const char*)w1t + o * 4;
    float* zp = g_z1 + ((size_t)b * TLEN + t0) * CHID + o;

    for (int tt = grp; tt < K1_T; tt += 16) {
        const unsigned* L = lists + tt * 104;
        const int cnt = counts[tt];
        float a0 = 0.0f, a1 = 0.0f, a2 = 0.0f, a3 = 0.0f;
        for (int p = 0; p < cnt; p += 4) {
            uint4 e = *(const uint4*)(L + p);
            float4 w0 = *(const float4*)(wb + e.x);
            float4 w1 = *(const float4*)(wb + e.y);
            float4 w2 = *(const float4*)(wb + e.z);
            float4 w3 = *(const float4*)(wb + e.w);
            a0 += w0.x; a1 += w0.y; a2 += w0.z; a3 += w0.w;
            a0 += w1.x; a1 += w1.y; a2 += w1.z; a3 += w1.w;
            a0 += w2.x; a1 += w2.y; a2 += w2.z; a3 += w2.w;
            a0 += w3.x; a1 += w3.y; a2 += w3.z; a3 += w3.w;
        }
        *(float4*)(zp + (size_t)tt * CHID) = make_float4(a0, a1, a2, a3);
    }
}

// =====================================================================
// LIF batch processors.  v = fma(v, 0.95f, z) — matches XLA contraction.
// =====================================================================
__device__ __forceinline__ void proc32_bits(float& v, const float (&z)[32],
                                            int tbase, float* __restrict__ so,
                                            unsigned* __restrict__ bw, int lane) {
    unsigned keep = 0;
    #pragma unroll
    for (int u8 = 0; u8 < 32; u8 += 8) {
        float sv[8];
        #pragma unroll
        for (int u = 0; u < 8; u++) {
            const int st = u8 + u;
            v = __fmaf_rn(v, 0.95f, z[st]);
            bool sp = (v >= 1.0f);
            sv[u] = sp ? 1.0f : 0.0f;
            unsigned bal = __ballot_sync(0xffffffffu, sp);
            keep = (lane == st) ? bal : keep;
            v = sp ? 0.0f : v;
        }
        *(float4*)(so + tbase + u8)     = make_float4(sv[0], sv[1], sv[2], sv[3]);
        *(float4*)(so + tbase + u8 + 4) = make_float4(sv[4], sv[5], sv[6], sv[7]);
    }
    bw[(size_t)(tbase + lane) * (CHID/32)] = keep;
}

__device__ __forceinline__ void proc32(float& v, const float (&z)[32],
                                       int tbase, float* __restrict__ so) {
    #pragma unroll
    for (int u8 = 0; u8 < 32; u8 += 8) {
        float sv[8];
        #pragma unroll
        for (int u = 0; u < 8; u++) {
            v = __fmaf_rn(v, 0.95f, z[u8 + u]);
            bool sp = (v >= 1.0f);
            sv[u] = sp ? 1.0f : 0.0f;
            v = sp ? 0.0f : v;
        }
        *(float4*)(so + tbase + u8)     = make_float4(sv[0], sv[1], sv[2], sv[3]);
        *(float4*)(so + tbase + u8 + 4) = make_float4(sv[4], sv[5], sv[6], sv[7]);
    }
}

// =====================================================================
// K2: layer-1 LIF scan. 16384 threads, block=64 (256 CTAs).
// 4 rotating 32-step register buffers (prefetch distance 3).
// =====================================================================
#define LD32(dst, zp, t) { _Pragma("unroll") \
    for (int u = 0; u < 32; u++) dst[u] = __ldg(zp + (size_t)((t) + u) * CHID); }

__global__ __launch_bounds__(64) void k2_scan1(float* __restrict__ out) {
    const int gid  = blockIdx.x * 64 + threadIdx.x;
    const int b    = gid >> 8;
    const int o    = gid & 255;
    const int lane = o & 31;
    const float* z  = g_z1 + (size_t)b * TLEN * CHID + o;
    float*       so = out + ((size_t)b * CHID + o) * TLEN;
    unsigned*    bw = g_s1bits + (size_t)b * TLEN * (CHID/32) + (o >> 5);

    float A[32], B[32], C[32], D[32];
    float v = 0.0f;
    LD32(A, z, 0); LD32(B, z, 32); LD32(C, z, 64);

    for (int bi = 0; bi < 64; bi += 4) {
        const int t = bi * 32;
        if (bi + 3 < 64) LD32(D, z, t + 96);
        proc32_bits(v, A, t, so, bw, lane);
        if (bi + 4 < 64) LD32(A, z, t + 128);
        proc32_bits(v, B, t + 32, so, bw, lane);
        if (bi + 5 < 64) LD32(B, z, t + 160);
        proc32_bits(v, C, t + 64, so, bw, lane);
        if (bi + 6 < 64) LD32(C, z, t + 192);
        proc32_bits(v, D, t + 96, so, bw, lane);
    }
}

// =====================================================================
// K3: layer-2 sparse GEMM from spike bits. CTA = (t-chunk 64, b);
// 768 threads = 8 groups x 96 lanes (3 full warps -> warp-uniform masks),
// lanes r>=80 gated off entirely. Results staged in an smem tile
// (stride 81: conflict-free both directions), then stored TRANSPOSED to
// g_z2[b][j][t] as float4 so K4 reads contiguously.
// =====================================================================
#define K3_T 64
__global__ __launch_bounds__(768) void k3_gemm2(const float* __restrict__ W2) {
    extern __shared__ char sm[];
    float*    w2t    = (float*)sm;                   // [257][81]+pad = 83344 B
    unsigned* lists  = (unsigned*)(sm + 83344);      // [64][264] u32 = 67584 B
    int*      counts = (int*)(sm + 150928);          // [64] = 256 B
    float*    ztile  = (float*)(sm + 151184);        // [64][81] = 20736 B

    const int tid = threadIdx.x;
    const int t0  = blockIdx.x * K3_T;
    const int b   = blockIdx.y;

    // W2 [80][256] -> w2t[o*81+j]; stride 81 odd -> conflict-free STS
    for (int idx = tid; idx < COUT * CHID; idx += 768) {
        int j = idx / CHID, o = idx % CHID;
        w2t[o * 81 + j] = W2[idx];
    }
    if (tid < 100) w2t[256 * 81 + tid] = 0.0f;

    if (tid < K3_T) {
        const unsigned* sb = g_s1bits + ((size_t)b * TLEN + t0 + tid) * 8;
        unsigned* L = lists + tid * 264;
        int c = 0;
        #pragma unroll
        for (int w = 0; w < 8; w++) {
            unsigned m = sb[w];
            while (m) {
                int k = __ffs(m) - 1;
                m &= m - 1;
                L[c++] = (unsigned)(((w << 5) + k) * 324);
            }
        }
        while (c & 3) L[c++] = (unsigned)(256 * 324);
        counts[tid] = c;
    }
    __syncthreads();

    const int grp = tid / 96;            // 0..7 (3 full warps each)
    const int r   = tid % 96;

    if (r < COUT) {                      // lanes 80..95 issue nothing
        const char* wb = (const char*)w2t + r * 4;
        for (int q = grp; q < K3_T / 2; q += 8) {
            const int tt = 2 * q;
            const unsigned* L0 = lists + tt * 264;
            const unsigned* L1 = L0 + 264;
            const int c0 = counts[tt], c1 = counts[tt + 1];
            const int cmin = c0 < c1 ? c0 : c1;
            float a0 = 0.0f, a1 = 0.0f;
            int p = 0;
            for (; p < cmin; p += 4) {
                uint4 e0 = *(const uint4*)(L0 + p);
                uint4 e1 = *(const uint4*)(L1 + p);
                a0 += *(const float*)(wb + e0.x);  a1 += *(const float*)(wb + e1.x);
                a0 += *(const float*)(wb + e0.y);  a1 += *(const float*)(wb + e1.y);
                a0 += *(const float*)(wb + e0.z);  a1 += *(const float*)(wb + e1.z);
                a0 += *(const float*)(wb + e0.w);  a1 += *(const float*)(wb + e1.w);
            }
            for (; p < c0; p += 4) {
                uint4 e0 = *(const uint4*)(L0 + p);
                a0 += *(const float*)(wb + e0.x);  a0 += *(const float*)(wb + e0.y);
                a0 += *(const float*)(wb + e0.z);  a0 += *(const float*)(wb + e0.w);
            }
            for (; p < c1; p += 4) {
                uint4 e1 = *(const uint4*)(L1 + p);
                a1 += *(const float*)(wb + e1.x);  a1 += *(const float*)(wb + e1.y);
                a1 += *(const float*)(wb + e1.z);  a1 += *(const float*)(wb + e1.w);
            }
            ztile[tt * 81 + r]       = a0;
            ztile[(tt + 1) * 81 + r] = a1;
        }
    }
    __syncthreads();

    // transposed store-out: g_z2[b][j][t0..], float4, coalesced
    float* zo = g_z2 + (size_t)b * COUT * TLEN + t0;
    for (int idx = tid; idx < COUT * (K3_T / 4); idx += 768) {
        int j = idx >> 4, q = idx & 15;
        float4 vv = make_float4(ztile[(4 * q + 0) * 81 + j],
                                ztile[(4 * q + 1) * 81 + j],
                                ztile[(4 * q + 2) * 81 + j],
                                ztile[(4 * q + 3) * 81 + j]);
        *(float4*)(zo + (size_t)j * TLEN + 4 * q) = vv;
    }
}

// =====================================================================
// K4: layer-2 LIF scan. g_z2 is [b][j][t] -> contiguous float4 loads.
// =====================================================================
#define LD32C(dst, zp, t) { _Pragma("unroll") \
    for (int u = 0; u < 8; u++) *(float4*)((dst) + 4 * u) = \
        __ldg((const float4*)((zp) + (t)) + u); }

__global__ __launch_bounds__(32) void k4_scan2(float* __restrict__ out) {
    const int gid = blockIdx.x * 32 + threadIdx.x;   // 0..5119
    const int b = gid / COUT;
    const int j = gid % COUT;
    const float* z  = g_z2 + ((size_t)b * COUT + j) * TLEN;
    float*       so = out + (size_t)BATCH * CHID * TLEN
                          + ((size_t)b * COUT + j) * TLEN;

    float A[32], B[32], C[32], D[32];
    float v = 0.0f;
    LD32C(A, z, 0); LD32C(B, z, 32); LD32C(C, z, 64);

    for (int bi = 0; bi < 64; bi += 4) {
        const int t = bi * 32;
        if (bi + 3 < 64) LD32C(D, z, t + 96);
        proc32(v, A, t, so);
        if (bi + 4 < 64) LD32C(A, z, t + 128);
        proc32(v, B, t + 32, so);
        if (bi + 5 < 64) LD32C(B, z, t + 160);
        proc32(v, C, t + 64, so);
        if (bi + 6 < 64) LD32C(C, z, t + 192);
        proc32(v, D, t + 96, so);
    }
}

// =====================================================================
extern "C" void kernel_launch(void* const* d_in, const int* in_sizes, int n_in,
                              void* d_out, int out_size) {
    const float* x  = (const float*)d_in[0];   // [64, 96, 2048]
    const float* W1 = (const float*)d_in[1];   // [256, 96]
    const float* W2 = (const float*)d_in[2];   // [80, 256]
    float* out = (float*)d_out;                // spk1 ++ spk2

    const int smem1 = 154144 + 512;            // 154656
    const int smem3 = 151184 + 20736;          // 171920
    cudaFuncSetAttribute(k1_gemm1, cudaFuncAttributeMaxDynamicSharedMemorySize, smem1);
    cudaFuncSetAttribute(k3_gemm2, cudaFuncAttributeMaxDynamicSharedMemorySize, smem3);

    k0_xbits<<<(BATCH * TLEN) / 256, 256>>>(x);
    k1_gemm1<<<dim3(TLEN / K1_T, BATCH), 1024, smem1>>>(W1);
    k2_scan1<<<(BATCH * CHID) / 64, 64>>>(out);
    k3_gemm2<<<dim3(TLEN / K3_T, BATCH), 768, smem3>>>(W2);
    k4_scan2<<<(BATCH * COUT) / 32, 32>>>(out);
}

// round 9
// speedup vs baseline: 1.5606x; 1.0317x over previous
#include <cuda_runtime.h>

#define BATCH 64
#define CIN   96
#define CHID  256
#define COUT  80
#define TLEN  2048

// ---- scratch (allocation-free rule: __device__ globals) ----
static __device__ float    g_z1[(size_t)BATCH * TLEN * CHID];          // 128 MiB  [b][t][o]
static __device__ float    g_z2[(size_t)BATCH * TLEN * COUT];          // 40 MiB   [b][j][t]
static __device__ unsigned g_xbits[(size_t)BATCH * TLEN * 4];          // 2 MiB
static __device__ unsigned g_s1bits[(size_t)BATCH * TLEN * (CHID/32)]; // 4 MiB

// =====================================================================
// K0: build 96-bit input-activity masks per (b,t). Coalesced LDGs.
// =====================================================================
__global__ __launch_bounds__(256) void k0_xbits(const float* __restrict__ x) {
    const int gid = blockIdx.x * 256 + threadIdx.x;   // 0 .. 64*2048-1
    const int b = gid >> 11;
    const int t = gid & 2047;
    const float* xp = x + (size_t)b * CIN * TLEN + t;
    unsigned m0 = 0, m1 = 0, m2 = 0;
    #pragma unroll
    for (int i = 0; i < 32; i++) if (__ldg(xp + (size_t)i * TLEN) != 0.0f)        m0 |= 1u << i;
    #pragma unroll
    for (int i = 0; i < 32; i++) if (__ldg(xp + (size_t)(i + 32) * TLEN) != 0.0f) m1 |= 1u << i;
    #pragma unroll
    for (int i = 0; i < 32; i++) if (__ldg(xp + (size_t)(i + 64) * TLEN) != 0.0f) m2 |= 1u << i;
    *(uint4*)&g_xbits[(size_t)gid * 4] = make_uint4(m0, m1, m2, 0u);
}

// =====================================================================
// K1: layer-1 sparse GEMM, o-SPLIT for occupancy.
// CTA = (t-chunk 128, o-half, b); 1024 threads; smem 78 KB -> 2 CTAs/SM
// (64 warps = 100% occ). Thread owns 4 adjacent o of its 128-o half
// (warp = 512B LDS.128, conflict-free). w1t stride 132 floats (528 B,
// 16B-aligned). Lists = uint16 byte offsets i*528 (<=50688 fits),
// zero-padded x4 (dummy row 96 = 0). Bit-exact ascending-i order.
// =====================================================================
#define K1_T 128
#define W1ST 528                      // bytes per w1t row (132 floats)
__global__ __launch_bounds__(1024, 2) void k1_gemm1(const float* __restrict__ W1) {
    extern __shared__ char sm[];
    float*          w1t    = (float*)sm;                    // [97][132] = 51216 B
    unsigned short* lists  = (unsigned short*)(sm + 51216); // [128][104] = 26624 B
    int*            counts = (int*)(sm + 77840);            // [128]

    const int tid = threadIdx.x;
    const int t0  = blockIdx.x * K1_T;
    const int o0  = blockIdx.y * 128;
    const int b   = blockIdx.z;

    // load this CTA's 128-o half of W1: coalesced LDG (rows of 96),
    // STS stride 528 B (8-way max, one-time cost)
    for (int idx = tid; idx < 128 * CIN; idx += 1024) {
        int ol = idx / CIN, i = idx % CIN;
        w1t[i * 132 + ol] = W1[(size_t)(o0 + ol) * CIN + i];
    }
    for (int idx = tid; idx < 132; idx += 1024) w1t[96 * 132 + idx] = 0.0f;

    if (tid < K1_T) {  // ascending-i byte-offset list for step t0+tid
        uint4 mw = *(const uint4*)&g_xbits[((size_t)b * TLEN + t0 + tid) * 4];
        unsigned short* L = lists + tid * 104;
        int c = 0;
        unsigned m = mw.x;
        while (m) { int k = __ffs(m) - 1; m &= m - 1; L[c++] = (unsigned short)(k * W1ST); }
        m = mw.y;
        while (m) { int k = __ffs(m) - 1; m &= m - 1; L[c++] = (unsigned short)((k + 32) * W1ST); }
        m = mw.z;
        while (m) { int k = __ffs(m) - 1; m &= m - 1; L[c++] = (unsigned short)((k + 64) * W1ST); }
        while (c & 3) L[c++] = (unsigned short)(96 * W1ST);
        counts[tid] = c;
    }
    __syncthreads();

    const int grp  = tid >> 5;         // 0..31: step interleave (1 warp each)
    const int lane = tid & 31;
    const char* wb = (const char*)w1t + lane * 16;   // this thread's 4-o base
    float* zp = g_z1 + ((size_t)b * TLEN + t0) * CHID + o0 + lane * 4;

    for (int tt = grp; tt < K1_T; tt += 32) {
        const unsigned short* L = lists + tt * 104;
        const int cnt = counts[tt];
        float a0 = 0.0f, a1 = 0.0f, a2 = 0.0f, a3 = 0.0f;
        for (int p = 0; p < cnt; p += 4) {
            uint2 e = *(const uint2*)(L + p);
            float4 w0 = *(const float4*)(wb + (e.x & 0xffff));
            float4 w1 = *(const float4*)(wb + (e.x >> 16));
            float4 w2 = *(const float4*)(wb + (e.y & 0xffff));
            float4 w3 = *(const float4*)(wb + (e.y >> 16));
            a0 += w0.x; a1 += w0.y; a2 += w0.z; a3 += w0.w;
            a0 += w1.x; a1 += w1.y; a2 += w1.z; a3 += w1.w;
            a0 += w2.x; a1 += w2.y; a2 += w2.z; a3 += w2.w;
            a0 += w3.x; a1 += w3.y; a2 += w3.z; a3 += w3.w;
        }
        *(float4*)(zp + (size_t)tt * CHID) = make_float4(a0, a1, a2, a3);
    }
}

// =====================================================================
// LIF batch processors.  v = fma(v, 0.95f, z) — matches XLA contraction.
// =====================================================================
__device__ __forceinline__ void proc32_bits(float& v, const float (&z)[32],
                                            int tbase, float* __restrict__ so,
                                            unsigned* __restrict__ bw, int lane) {
    unsigned keep = 0;
    #pragma unroll
    for (int u8 = 0; u8 < 32; u8 += 8) {
        float sv[8];
        #pragma unroll
        for (int u = 0; u < 8; u++) {
            const int st = u8 + u;
            v = __fmaf_rn(v, 0.95f, z[st]);
            bool sp = (v >= 1.0f);
            sv[u] = sp ? 1.0f : 0.0f;
            unsigned bal = __ballot_sync(0xffffffffu, sp);
            keep = (lane == st) ? bal : keep;
            v = sp ? 0.0f : v;
        }
        *(float4*)(so + tbase + u8)     = make_float4(sv[0], sv[1], sv[2], sv[3]);
        *(float4*)(so + tbase + u8 + 4) = make_float4(sv[4], sv[5], sv[6], sv[7]);
    }
    bw[(size_t)(tbase + lane) * (CHID/32)] = keep;
}

__device__ __forceinline__ void proc32(float& v, const float (&z)[32],
                                       int tbase, float* __restrict__ so) {
    #pragma unroll
    for (int u8 = 0; u8 < 32; u8 += 8) {
        float sv[8];
        #pragma unroll
        for (int u = 0; u < 8; u++) {
            v = __fmaf_rn(v, 0.95f, z[u8 + u]);
            bool sp = (v >= 1.0f);
            sv[u] = sp ? 1.0f : 0.0f;
            v = sp ? 0.0f : v;
        }
        *(float4*)(so + tbase + u8)     = make_float4(sv[0], sv[1], sv[2], sv[3]);
        *(float4*)(so + tbase + u8 + 4) = make_float4(sv[4], sv[5], sv[6], sv[7]);
    }
}

// =====================================================================
// K2: layer-1 LIF scan. 16384 threads, block=64 (256 CTAs).
// 4 rotating 32-step register buffers (prefetch distance 3).
// =====================================================================
#define LD32(dst, zp, t) { _Pragma("unroll") \
    for (int u = 0; u < 32; u++) dst[u] = __ldg(zp + (size_t)((t) + u) * CHID); }

__global__ __launch_bounds__(64) void k2_scan1(float* __restrict__ out) {
    const int gid  = blockIdx.x * 64 + threadIdx.x;
    const int b    = gid >> 8;
    const int o    = gid & 255;
    const int lane = o & 31;
    const float* z  = g_z1 + (size_t)b * TLEN * CHID + o;
    float*       so = out + ((size_t)b * CHID + o) * TLEN;
    unsigned*    bw = g_s1bits + (size_t)b * TLEN * (CHID/32) + (o >> 5);

    float A[32], B[32], C[32], D[32];
    float v = 0.0f;
    LD32(A, z, 0); LD32(B, z, 32); LD32(C, z, 64);

    for (int bi = 0; bi < 64; bi += 4) {
        const int t = bi * 32;
        if (bi + 3 < 64) LD32(D, z, t + 96);
        proc32_bits(v, A, t, so, bw, lane);
        if (bi + 4 < 64) LD32(A, z, t + 128);
        proc32_bits(v, B, t + 32, so, bw, lane);
        if (bi + 5 < 64) LD32(B, z, t + 160);
        proc32_bits(v, C, t + 64, so, bw, lane);
        if (bi + 6 < 64) LD32(C, z, t + 192);
        proc32_bits(v, D, t + 96, so, bw, lane);
    }
}

// =====================================================================
// K3: layer-2 sparse GEMM from spike bits.
// TRANSPOSED weights: w2t[j][o], row stride 257 floats (1028 B, odd
// stride -> conflict-free lane reads). List entry = byte offset 4*o
// (max 1024 -> uint16, zero arithmetic in hot loop). K3_T=32 keeps
// smem at 110 KB -> 2 CTAs/SM (48 warps, was 24).
// 768 thr = 8 groups x 96 lanes (3 full warps, r>=80 gated off).
// Dummy entry o=256 -> zeroed column 256. Results staged in ztile then
// stored TRANSPOSED to g_z2[b][j][t] as float4.
// =====================================================================
#define K3_T 32
__global__ __launch_bounds__(768, 2) void k3_gemm2(const float* __restrict__ W2) {
    extern __shared__ char sm[];
    float*          w2t    = (float*)sm;                    // [80][257] = 82240 B
    unsigned short* lists  = (unsigned short*)(sm + 82240); // [32][264] = 16896 B
    int*            counts = (int*)(sm + 99136);            // [32] = 128 B
    float*          ztile  = (float*)(sm + 99264);          // [32][81] = 10368 B

    const int tid = threadIdx.x;
    const int t0  = blockIdx.x * K3_T;
    const int b   = blockIdx.y;

    // W2 [80][256] row-major -> w2t[j*257 + o]: coalesced LDG + linear STS
    for (int idx = tid; idx < COUT * CHID; idx += 768) {
        int j = idx >> 8, o = idx & 255;
        w2t[j * 257 + o] = W2[idx];
    }
    for (int idx = tid; idx < COUT; idx += 768) w2t[idx * 257 + 256] = 0.0f;

    if (tid < K3_T) {  // ascending-o list, entries = 4*o (byte offset)
        const unsigned* sb = g_s1bits + ((size_t)b * TLEN + t0 + tid) * 8;
        unsigned short* L = lists + tid * 264;
        int c = 0;
        #pragma unroll
        for (int w = 0; w < 8; w++) {
            unsigned m = sb[w];
            while (m) {
                int k = __ffs(m) - 1;
                m &= m - 1;
                L[c++] = (unsigned short)(((w << 5) + k) << 2);
            }
        }
        while (c & 3) L[c++] = (unsigned short)(256 << 2);
        counts[tid] = c;
    }
    __syncthreads();

    const int grp = tid / 96;            // 0..7 (3 full warps each)
    const int r   = tid % 96;

    if (r < COUT) {                      // lanes 80..95 issue nothing
        const char* wb = (const char*)(w2t + r * 257);
        for (int q = grp; q < K3_T / 2; q += 8) {
            const int tt = 2 * q;
            const unsigned short* L0 = lists + tt * 264;
            const unsigned short* L1 = L0 + 264;
            const int c0 = counts[tt], c1 = counts[tt + 1];
            const int cmin = c0 < c1 ? c0 : c1;
            float a0 = 0.0f, a1 = 0.0f;
            int p = 0;
            for (; p < cmin; p += 4) {         // two interleaved chains
                uint2 e0 = *(const uint2*)(L0 + p);
                uint2 e1 = *(const uint2*)(L1 + p);
                a0 += *(const float*)(wb + (e0.x & 0xffff));
                a1 += *(const float*)(wb + (e1.x & 0xffff));
                a0 += *(const float*)(wb + (e0.x >> 16));
                a1 += *(const float*)(wb + (e1.x >> 16));
                a0 += *(const float*)(wb + (e0.y & 0xffff));
                a1 += *(const float*)(wb + (e1.y & 0xffff));
                a0 += *(const float*)(wb + (e0.y >> 16));
                a1 += *(const float*)(wb + (e1.y >> 16));
            }
            for (; p < c0; p += 4) {
                uint2 e0 = *(const uint2*)(L0 + p);
                a0 += *(const float*)(wb + (e0.x & 0xffff));
                a0 += *(const float*)(wb + (e0.x >> 16));
                a0 += *(const float*)(wb + (e0.y & 0xffff));
                a0 += *(const float*)(wb + (e0.y >> 16));
            }
            for (; p < c1; p += 4) {
                uint2 e1 = *(const uint2*)(L1 + p);
                a1 += *(const float*)(wb + (e1.x & 0xffff));
                a1 += *(const float*)(wb + (e1.x >> 16));
                a1 += *(const float*)(wb + (e1.y & 0xffff));
                a1 += *(const float*)(wb + (e1.y >> 16));
            }
            ztile[tt * 81 + r]       = a0;
            ztile[(tt + 1) * 81 + r] = a1;
        }
    }
    __syncthreads();

    // transposed store-out: g_z2[b][j][t0..], float4, coalesced
    float* zo = g_z2 + (size_t)b * COUT * TLEN + t0;
    for (int idx = tid; idx < COUT * (K3_T / 4); idx += 768) {
        int j = idx >> 3, q = idx & 7;
        float4 vv = make_float4(ztile[(4 * q + 0) * 81 + j],
                                ztile[(4 * q + 1) * 81 + j],
                                ztile[(4 * q + 2) * 81 + j],
                                ztile[(4 * q + 3) * 81 + j]);
        *(float4*)(zo + (size_t)j * TLEN + 4 * q) = vv;
    }
}

// =====================================================================
// K4: layer-2 LIF scan. g_z2 is [b][j][t] -> contiguous float4 loads.
// =====================================================================
#define LD32C(dst, zp, t) { _Pragma("unroll") \
    for (int u = 0; u < 8; u++) *(float4*)((dst) + 4 * u) = \
        __ldg((const float4*)((zp) + (t)) + u); }

__global__ __launch_bounds__(32) void k4_scan2(float* __restrict__ out) {
    const int gid = blockIdx.x * 32 + threadIdx.x;   // 0..5119
    const int b = gid / COUT;
    const int j = gid % COUT;
    const float* z  = g_z2 + ((size_t)b * COUT + j) * TLEN;
    float*       so = out + (size_t)BATCH * CHID * TLEN
                          + ((size_t)b * COUT + j) * TLEN;

    float A[32], B[32], C[32], D[32];
    float v = 0.0f;
    LD32C(A, z, 0); LD32C(B, z, 32); LD32C(C, z, 64);

    for (int bi = 0; bi < 64; bi += 4) {
        const int t = bi * 32;
        if (bi + 3 < 64) LD32C(D, z, t + 96);
        proc32(v, A, t, so);
        if (bi + 4 < 64) LD32C(A, z, t + 128);
        proc32(v, B, t + 32, so);
        if (bi + 5 < 64) LD32C(B, z, t + 160);
        proc32(v, C, t + 64, so);
        if (bi + 6 < 64) LD32C(C, z, t + 192);
        proc32(v, D, t + 96, so);
    }
}

// =====================================================================
extern "C" void kernel_launch(void* const* d_in, const int* in_sizes, int n_in,
                              void* d_out, int out_size) {
    const float* x  = (const float*)d_in[0];   // [64, 96, 2048]
    const float* W1 = (const float*)d_in[1];   // [256, 96]
    const float* W2 = (const float*)d_in[2];   // [80, 256]
    float* out = (float*)d_out;                // spk1 ++ spk2

    const int smem1 = 77840 + 512;             // 78352  -> 2 CTAs/SM
    const int smem3 = 99264 + 10368;           // 109632 -> 2 CTAs/SM
    cudaFuncSetAttribute(k1_gemm1, cudaFuncAttributeMaxDynamicSharedMemorySize, smem1);
    cudaFuncSetAttribute(k3_gemm2, cudaFuncAttributeMaxDynamicSharedMemorySize, smem3);

    k0_xbits<<<(BATCH * TLEN) / 256, 256>>>(x);
    k1_gemm1<<<dim3(TLEN / K1_T, 2, BATCH), 1024, smem1>>>(W1);
    k2_scan1<<<(BATCH * CHID) / 64, 64>>>(out);
    k3_gemm2<<<dim3(TLEN / K3_T, BATCH), 768, smem3>>>(W2);
    k4_scan2<<<(BATCH * COUT) / 32, 32>>>(out);
}